// round 3
// baseline (speedup 1.0000x reference)
#include <cuda_runtime.h>
#include <cstdint>
#include <cstddef>

#define MTOT 8192
#define KTOT 4096
#define NTOT 16384

#define BM 128
#define BN 128
#define BK 64
#define STAGES 5
#define KITERS (KTOT / BK)          // 64
#define APAD 80                     // padded SMEM row stride (conflict-free)
#define A_STAGE (256 * APAD)        // 2 planes x 128 rows
#define B_STAGE (128 * APAD)
#define STAGE_B (A_STAGE + B_STAGE) // 30720
#define SMEM_TOTAL (STAGES * STAGE_B)

// ---------------- scratch ----------------
__device__ int8_t g_xhi[(size_t)MTOT * KTOT];
__device__ int8_t g_xlo[(size_t)MTOT * KTOT];
__device__ float  g_xscale[MTOT];
__device__ int8_t g_w8[(size_t)NTOT * KTOT];

// ---------------- PTX helpers (base sm_80+ ISA only) ----------------
__device__ __forceinline__ uint32_t smem_u32(const void* p) {
    uint32_t a;
    asm("{ .reg .u64 t; cvta.to.shared.u64 t, %1; cvt.u32.u64 %0, t; }" : "=r"(a) : "l"(p));
    return a;
}
__device__ __forceinline__ uint32_t lds32(uint32_t a) {
    uint32_t v;
    asm volatile("ld.shared.b32 %0, [%1];" : "=r"(v) : "r"(a));
    return v;
}
#define CP16(dst, src) \
    asm volatile("cp.async.cg.shared.global [%0], [%1], 16;" :: "r"(dst), "l"(src) : "memory")
#define CP_COMMIT() asm volatile("cp.async.commit_group;" ::: "memory")
#define CP_WAIT(n)  asm volatile("cp.async.wait_group %0;" :: "n"(n) : "memory")

__device__ __forceinline__ void mma_s8(int* d, const uint32_t* a, const uint32_t* b) {
    asm volatile(
        "mma.sync.aligned.m16n8k32.row.col.s32.s8.s8.s32 "
        "{%0,%1,%2,%3}, {%4,%5,%6,%7}, {%8,%9}, {%0,%1,%2,%3};"
        : "+r"(d[0]), "+r"(d[1]), "+r"(d[2]), "+r"(d[3])
        : "r"(a[0]), "r"(a[1]), "r"(a[2]), "r"(a[3]), "r"(b[0]), "r"(b[1]));
}

__device__ __forceinline__ uint32_t pack4(int a, int b, int c, int d) {
    return (a & 0xff) | ((b & 0xff) << 8) | ((c & 0xff) << 16) | ((d & 0xff) << 24);
}

// ---------------- kernel 1: quantize x rows to dual int8 planes ----------------
__global__ void __launch_bounds__(256) qx_kernel(const float* __restrict__ x) {
    __shared__ float red[8];
    __shared__ float s_inv;
    int row = blockIdx.x;
    int t = threadIdx.x;
    const float4* xr = (const float4*)x + (size_t)row * 1024;
    float4 v[4];
    float m = 0.f;
#pragma unroll
    for (int i = 0; i < 4; i++) {
        v[i] = xr[t * 4 + i];
        m = fmaxf(m, fmaxf(fmaxf(fabsf(v[i].x), fabsf(v[i].y)),
                           fmaxf(fabsf(v[i].z), fabsf(v[i].w))));
    }
#pragma unroll
    for (int o = 16; o; o >>= 1) m = fmaxf(m, __shfl_xor_sync(~0u, m, o));
    if ((t & 31) == 0) red[t >> 5] = m;
    __syncthreads();
    if (t == 0) {
        float mm = 1e-30f;
#pragma unroll
        for (int i = 0; i < 8; i++) mm = fmaxf(mm, red[i]);
        s_inv = 32512.f / mm;
        g_xscale[row] = mm * (1.f / 32512.f);
    }
    __syncthreads();
    float inv = s_inv;

    const float* fv = (const float*)v;
    uint32_t hw[4], lw[4];
#pragma unroll
    for (int w = 0; w < 4; w++) {
        int hb[4], lb[4];
#pragma unroll
        for (int e = 0; e < 4; e++) {
            int iv = __float2int_rn(fv[w * 4 + e] * inv);
            iv = max(-32512, min(32512, iv));
            int h = (iv + 128) >> 8;            // round-to-nearest hi
            hb[e] = h;
            lb[e] = iv - (h << 8);              // lo in [-128,127]
        }
        hw[w] = pack4(hb[0], hb[1], hb[2], hb[3]);
        lw[w] = pack4(lb[0], lb[1], lb[2], lb[3]);
    }
    size_t base = (size_t)row * 4096 + t * 16;
    *(uint4*)(g_xhi + base) = make_uint4(hw[0], hw[1], hw[2], hw[3]);
    *(uint4*)(g_xlo + base) = make_uint4(lw[0], lw[1], lw[2], lw[3]);
}

// ---------------- kernel 2: W int32 -> int8 ----------------
__global__ void __launch_bounds__(256) qw_kernel(const int* __restrict__ wq) {
    int n = blockIdx.x;
    int t = threadIdx.x;
    const int4* wr = (const int4*)wq + (size_t)n * 1024;
    uint32_t pw[4];
#pragma unroll
    for (int w = 0; w < 4; w++) {
        int4 a = wr[t * 4 + w];
        pw[w] = pack4(a.x, a.y, a.z, a.w);
    }
    *(uint4*)(g_w8 + (size_t)n * 4096 + t * 16) = make_uint4(pw[0], pw[1], pw[2], pw[3]);
}

// ---------------- kernel 3: dual-plane int8 IMMA GEMM ----------------
__global__ void __launch_bounds__(512, 1) gemm_kernel(
    float* __restrict__ out, const float* __restrict__ wscale,
    const float* __restrict__ bias)
{
    extern __shared__ uint8_t smem[];

    int tid = threadIdx.x;
    int wid = tid >> 5;
    int lane = tid & 31;
    int wm = wid >> 2;          // 0..3
    int wn = wid & 3;           // 0..3
    int lr = lane >> 2;         // 0..7
    int lc = lane & 3;          // 0..3

    // GM=8 M-grouped raster over 64 x 128 tile grid
    int gid = blockIdx.x;
    int group = gid >> 10;              // / (8*128)
    int rem = gid & 1023;
    int pid_m = group * 8 + (rem & 7);
    int pid_n = rem >> 3;

    const int8_t* Ahi = g_xhi + (size_t)pid_m * 128 * 4096;
    const int8_t* Alo = g_xlo + (size_t)pid_m * 128 * 4096;
    const int8_t* Bp  = g_w8  + (size_t)pid_n * 128 * 4096;

    // per-thread load coords (fixed)
    int arow0 = tid >> 2;           // 0..127  (hi plane)
    int ach = (tid & 3) * 16;
    int brow = tid >> 2;

    // issue one stage of cp.async
    auto issue = [&](int it) {
        uint8_t* As = smem + (it % STAGES) * STAGE_B;
        uint8_t* Bs = As + A_STAGE;
        int k0 = it * BK;
        CP16(smem_u32(As + arow0 * APAD + ach),
             Ahi + (size_t)arow0 * 4096 + k0 + ach);
        CP16(smem_u32(As + (128 + arow0) * APAD + ach),
             Alo + (size_t)arow0 * 4096 + k0 + ach);
        CP16(smem_u32(Bs + brow * APAD + ach),
             Bp + (size_t)brow * 4096 + k0 + ach);
    };

#pragma unroll
    for (int s = 0; s < STAGES - 1; s++) {
        issue(s);
        CP_COMMIT();
    }

    int acc[2][2][4][4];
#pragma unroll
    for (int p = 0; p < 2; p++)
#pragma unroll
        for (int f = 0; f < 2; f++)
#pragma unroll
            for (int g = 0; g < 4; g++)
#pragma unroll
                for (int e = 0; e < 4; e++) acc[p][f][g][e] = 0;

    for (int it = 0; it < KITERS; it++) {
        CP_WAIT(STAGES - 2);
        __syncthreads();
        if (it + STAGES - 1 < KITERS) issue(it + STAGES - 1);
        CP_COMMIT();

        uint32_t aBase = smem_u32(smem + (it % STAGES) * STAGE_B);
        uint32_t bBase = aBase + A_STAGE;

#pragma unroll
        for (int ks = 0; ks < 2; ks++) {
            uint32_t bf[4][2];
#pragma unroll
            for (int g = 0; g < 4; g++) {
                uint32_t ba = bBase + (wn * 32 + g * 8 + lr) * APAD + ks * 32 + lc * 4;
                bf[g][0] = lds32(ba);
                bf[g][1] = lds32(ba + 16);
            }
#pragma unroll
            for (int p = 0; p < 2; p++) {
#pragma unroll
                for (int f = 0; f < 2; f++) {
                    uint32_t aa = aBase + (p * 128 + wm * 32 + f * 16 + lr) * APAD
                                + ks * 32 + lc * 4;
                    uint32_t af[4];
                    af[0] = lds32(aa);
                    af[1] = lds32(aa + 8 * APAD);
                    af[2] = lds32(aa + 16);
                    af[3] = lds32(aa + 8 * APAD + 16);
#pragma unroll
                    for (int g = 0; g < 4; g++)
                        mma_s8(acc[p][f][g], af, bf[g]);
                }
            }
        }
    }

    // ---------------- epilogue: combine planes, dequant, bias ----------------
#pragma unroll
    for (int f = 0; f < 2; f++) {
        int gm0 = pid_m * 128 + wm * 32 + f * 16 + lr;
        float xs0 = g_xscale[gm0];
        float xs1 = g_xscale[gm0 + 8];
        float* o0 = out + (size_t)gm0 * NTOT + pid_n * 128;
        float* o1 = o0 + (size_t)8 * NTOT;
#pragma unroll
        for (int g = 0; g < 4; g++) {
            int nc = wn * 32 + g * 8 + lc * 2;
            int gn = pid_n * 128 + nc;
            float w0 = wscale[gn], w1 = wscale[gn + 1];
            float b0 = bias[gn],   b1 = bias[gn + 1];
            float v00 = fmaf(256.f, (float)acc[0][f][g][0], (float)acc[1][f][g][0]);
            float v01 = fmaf(256.f, (float)acc[0][f][g][1], (float)acc[1][f][g][1]);
            float v10 = fmaf(256.f, (float)acc[0][f][g][2], (float)acc[1][f][g][2]);
            float v11 = fmaf(256.f, (float)acc[0][f][g][3], (float)acc[1][f][g][3]);
            float2 r0, r1;
            r0.x = fmaf(v00 * xs0, w0, b0);
            r0.y = fmaf(v01 * xs0, w1, b1);
            r1.x = fmaf(v10 * xs1, w0, b0);
            r1.y = fmaf(v11 * xs1, w1, b1);
            *(float2*)(o0 + nc) = r0;
            *(float2*)(o1 + nc) = r1;
        }
    }
}

// ---------------- launch ----------------
extern "C" void kernel_launch(void* const* d_in, const int* in_sizes, int n_in,
                              void* d_out, int out_size) {
    const float* x      = (const float*)d_in[0];
    const int*   wq     = (const int*)d_in[1];
    const float* wscale = (const float*)d_in[2];
    const float* bias   = (const float*)d_in[3];
    float* out = (float*)d_out;

    cudaFuncSetAttribute(gemm_kernel, cudaFuncAttributeMaxDynamicSharedMemorySize, SMEM_TOTAL);

    qx_kernel<<<MTOT, 256>>>(x);
    qw_kernel<<<NTOT, 256>>>(wq);
    gemm_kernel<<<8192, 512, SMEM_TOTAL>>>(out, wscale, bias);
}

// round 4
// speedup vs baseline: 5.1368x; 5.1368x over previous
#include <cuda_runtime.h>
#include <cuda_fp16.h>
#include <cstdint>
#include <cstddef>

#define MTOT 8192
#define KTOT 4096
#define NTOT 16384

#define BM 128
#define BN 256
#define BK 64                      // halves per k-chunk
#define STAGES 4
#define KIT (KTOT / BK)            // 64
#define ASTRIDE 144                // 128B row + 16B pad
#define A_STAGE (128 * ASTRIDE)    // 18432
#define B_STAGE (256 * ASTRIDE)    // 36864
#define STG_B (A_STAGE + B_STAGE)  // 55296
#define SMEM_TOTAL (STAGES * STG_B)

// ---------------- scratch ----------------
__device__ __half g_xh[(size_t)MTOT * KTOT];   // 64 MB
__device__ __half g_wh[(size_t)NTOT * KTOT];   // 128 MB

// ---------------- PTX helpers ----------------
__device__ __forceinline__ uint32_t smem_u32(const void* p) {
    uint32_t a;
    asm("{ .reg .u64 t; cvta.to.shared.u64 t, %1; cvt.u32.u64 %0, t; }" : "=r"(a) : "l"(p));
    return a;
}
#define CP16(dst, src) \
    asm volatile("cp.async.cg.shared.global [%0], [%1], 16;" :: "r"(dst), "l"(src) : "memory")
#define CP_COMMIT() asm volatile("cp.async.commit_group;" ::: "memory")
#define CP_WAIT(n)  asm volatile("cp.async.wait_group %0;" :: "n"(n) : "memory")

__device__ __forceinline__ void ldsm_x4(uint32_t* r, uint32_t addr) {
    asm volatile("ldmatrix.sync.aligned.m8n8.x4.shared.b16 {%0,%1,%2,%3}, [%4];"
                 : "=r"(r[0]), "=r"(r[1]), "=r"(r[2]), "=r"(r[3]) : "r"(addr));
}
__device__ __forceinline__ void mma_f16(float* d, const uint32_t* a, const uint32_t* b) {
    asm volatile(
        "mma.sync.aligned.m16n8k16.row.col.f32.f16.f16.f32 "
        "{%0,%1,%2,%3}, {%4,%5,%6,%7}, {%8,%9}, {%0,%1,%2,%3};"
        : "+f"(d[0]), "+f"(d[1]), "+f"(d[2]), "+f"(d[3])
        : "r"(a[0]), "r"(a[1]), "r"(a[2]), "r"(a[3]), "r"(b[0]), "r"(b[1]));
}

// ---------------- kernel 1: x fp32 -> fp16 ----------------
__global__ void __launch_bounds__(256) cx_kernel(const float* __restrict__ x) {
    size_t idx = (size_t)blockIdx.x * 256 + threadIdx.x;   // one uint4 (8 halves) per thread
    const float4* xi = (const float4*)x;
    float4 v0 = xi[idx * 2];
    float4 v1 = xi[idx * 2 + 1];
    __half2 h[4];
    h[0] = __float22half2_rn(make_float2(v0.x, v0.y));
    h[1] = __float22half2_rn(make_float2(v0.z, v0.w));
    h[2] = __float22half2_rn(make_float2(v1.x, v1.y));
    h[3] = __float22half2_rn(make_float2(v1.z, v1.w));
    ((uint4*)g_xh)[idx] = *(uint4*)h;
}

// ---------------- kernel 2: W int32 -> fp16 (exact) ----------------
__global__ void __launch_bounds__(256) cw_kernel(const int* __restrict__ wq) {
    size_t idx = (size_t)blockIdx.x * 256 + threadIdx.x;
    const int4* wi = (const int4*)wq;
    int4 v0 = wi[idx * 2];
    int4 v1 = wi[idx * 2 + 1];
    __half h[8];
    h[0] = __int2half_rn(v0.x); h[1] = __int2half_rn(v0.y);
    h[2] = __int2half_rn(v0.z); h[3] = __int2half_rn(v0.w);
    h[4] = __int2half_rn(v1.x); h[5] = __int2half_rn(v1.y);
    h[6] = __int2half_rn(v1.z); h[7] = __int2half_rn(v1.w);
    ((uint4*)g_wh)[idx] = *(uint4*)h;
}

// ---------------- kernel 3: fp16 HMMA GEMM ----------------
__global__ void __launch_bounds__(512, 1) gemm_kernel(
    float* __restrict__ out, const float* __restrict__ wscale,
    const float* __restrict__ bias)
{
    extern __shared__ uint8_t smem[];

    int tid = threadIdx.x;
    int wid = tid >> 5;
    int lane = tid & 31;
    int wm = wid >> 2;          // 0..3
    int wn = wid & 3;           // 0..3

    // GM=8 M-grouped raster over 64(m) x 64(n) tile grid
    int gid = blockIdx.x;
    int group = gid >> 9;
    int rem = gid & 511;
    int pid_m = group * 8 + (rem & 7);
    int pid_n = rem >> 3;

    const __half* Ab = g_xh + (size_t)pid_m * BM * KTOT;
    const __half* Bb = g_wh + (size_t)pid_n * BN * KTOT;

    uint32_t smem0 = smem_u32(smem);

    // cp.async: 3072 16B chunks per stage, 6 per thread
    auto issue = [&](int it) {
        uint32_t st = smem0 + (it % STAGES) * STG_B;
        int k0 = it * BK;
#pragma unroll
        for (int j = 0; j < 6; j++) {
            int c = tid + j * 512;
            if (c < 1024) {               // A: 128 rows x 8 chunks
                int row = c >> 3, col = c & 7;
                CP16(st + row * ASTRIDE + col * 16,
                     Ab + (size_t)row * KTOT + k0 + col * 8);
            } else {                      // B: 256 rows x 8 chunks
                int cc = c - 1024;
                int row = cc >> 3, col = cc & 7;
                CP16(st + A_STAGE + row * ASTRIDE + col * 16,
                     Bb + (size_t)row * KTOT + k0 + col * 8);
            }
        }
    };

#pragma unroll
    for (int s = 0; s < STAGES - 1; s++) {
        issue(s);
        CP_COMMIT();
    }

    float acc[2][8][4];
#pragma unroll
    for (int f = 0; f < 2; f++)
#pragma unroll
        for (int g = 0; g < 8; g++)
#pragma unroll
            for (int e = 0; e < 4; e++) acc[f][g][e] = 0.f;

    // ldmatrix lane addressing (precomputed per-thread offsets)
    int j8 = lane >> 3;           // matrix id 0..3
    int r8 = lane & 7;            // row within matrix
    // A x4: matrices (m0-7,k0-7),(m8-15,k0-7),(m0-7,k8-15),(m8-15,k8-15)
    int a_row = wm * 32 + (j8 & 1) * 8 + r8;
    int a_koff = (j8 >> 1) * 16;
    // B x4 (no trans; W is k-contiguous): (n0-7,k0-7),(n0-7,k8-15),(n8-15,k0-7),(n8-15,k8-15)
    int b_row = wn * 64 + (j8 >> 1) * 8 + r8;
    int b_koff = (j8 & 1) * 16;

    for (int it = 0; it < KIT; it++) {
        CP_WAIT(STAGES - 2);
        __syncthreads();
        if (it + STAGES - 1 < KIT) issue(it + STAGES - 1);
        CP_COMMIT();

        uint32_t aB = smem0 + (it % STAGES) * STG_B;
        uint32_t bB = aB + A_STAGE;

#pragma unroll
        for (int ks = 0; ks < 4; ks++) {
            uint32_t a[2][4];
#pragma unroll
            for (int f = 0; f < 2; f++)
                ldsm_x4(a[f], aB + (a_row + f * 16) * ASTRIDE + ks * 32 + a_koff);
            uint32_t b[4][4];
#pragma unroll
            for (int gg = 0; gg < 4; gg++)
                ldsm_x4(b[gg], bB + (b_row + gg * 16) * ASTRIDE + ks * 32 + b_koff);
#pragma unroll
            for (int f = 0; f < 2; f++)
#pragma unroll
                for (int g = 0; g < 8; g++)
                    mma_f16(acc[f][g], a[f], b[g >> 1] + (g & 1) * 2);
        }
    }

    // ---------------- epilogue: dequant + bias ----------------
    int lr = lane >> 2;          // 0..7
    int lc2 = (lane & 3) * 2;    // 0,2,4,6
#pragma unroll
    for (int f = 0; f < 2; f++) {
        int gm = pid_m * BM + wm * 32 + f * 16 + lr;
        float* o0 = out + (size_t)gm * NTOT + pid_n * BN;
        float* o1 = o0 + (size_t)8 * NTOT;
#pragma unroll
        for (int g = 0; g < 8; g++) {
            int nc = wn * 64 + g * 8 + lc2;
            int gn = pid_n * BN + nc;
            float w0 = __ldg(wscale + gn), w1 = __ldg(wscale + gn + 1);
            float b0 = __ldg(bias + gn),   b1 = __ldg(bias + gn + 1);
            float2 r0, r1;
            r0.x = fmaf(acc[f][g][0], w0, b0);
            r0.y = fmaf(acc[f][g][1], w1, b1);
            r1.x = fmaf(acc[f][g][2], w0, b0);
            r1.y = fmaf(acc[f][g][3], w1, b1);
            *(float2*)(o0 + nc) = r0;
            *(float2*)(o1 + nc) = r1;
        }
    }
}

// ---------------- launch ----------------
extern "C" void kernel_launch(void* const* d_in, const int* in_sizes, int n_in,
                              void* d_out, int out_size) {
    const float* x      = (const float*)d_in[0];
    const int*   wq     = (const int*)d_in[1];
    const float* wscale = (const float*)d_in[2];
    const float* bias   = (const float*)d_in[3];
    float* out = (float*)d_out;

    cudaFuncSetAttribute(gemm_kernel, cudaFuncAttributeMaxDynamicSharedMemorySize, SMEM_TOTAL);

    cx_kernel<<<(int)((size_t)MTOT * KTOT / 8 / 256), 256>>>(x);
    cw_kernel<<<(int)((size_t)NTOT * KTOT / 8 / 256), 256>>>(wq);
    gemm_kernel<<<4096, 512, SMEM_TOTAL>>>(out, wscale, bias);
}